// round 7
// baseline (speedup 1.0000x reference)
#include <cuda_runtime.h>
#include <cuda_fp16.h>

// TCLoss, N=2048, D=64.
// y_ijd = LOG2E * log N(z_i,d ; m_j,d, exp(lv_j,d)) = a_jd*q_id + b_jd*z_id + g_jd
//   with q = z^2.
// out = mean_i [ LN2*( sum_d log2 sum_j 2^y  -  log2sumexp2_j S_ij ) ],
//   S_ij = sum_d y_ijd = q_i . a_j + z_i . b_j + Gsum_j   <-- a GEMM!
//
// k0 prep: coeffs packed for kB (AB float4, G float2); GEMM operands
//          qzT[128][2048] = [q|z] transposed, abT[128][2048] = [a|b] transposed,
//          Gsum_j (segmented warp reduce).
// kA: S-GEMM (128x128 tile, 8x8 micro, K=128 fp32 FMA) + fused tile-LSE
//     epilogue (row max via 16-lane butterfly, f16x2 exp, sum butterfly) ->
//     per-(i, jtile) partials (m, s), 16 tiles per i.
// kB: per-dim path only (scalar path removed). Warp owns 4 i's, lane owns
//     dims {2l,2l+1}; 64-j smem tile; f16x2 exps, half2 pair accumulation,
//     fp32 flush every 8 j.
// kR: per-i merge of 32 per-dim chunks + 16 scalar tile partials.  kF: mean.

#define LOG2E   1.44269504088896340736f
#define LN2     0.69314718055994530942f
#define LOG2PI  1.83787706640934548356f

#define NPTS    2048
#define DDIM    64
#define TJ      64                   // j's per kB chunk
#define NCHUNK  (NPTS / TJ)          // 32
#define IPB     32                   // i's per kB block (8 warps x 4)
#define NGROUP  (NPTS / IPB)         // 64
#define NUNITS  (NGROUP * NCHUNK)    // 2048
#define NBLOCKS_B 444                // 148 SMs x 3 resident
#define KC      32                   // GEMM K chunk
#define NJT     16                   // j-tiles (2048/128)

// Static scratch (no allocation).
__device__ float4 g_cAB[NPTS * DDIM / 2];       // (a0,a1,b0,b1) per (j, dim-pair)
__device__ float2 g_cG[NPTS * DDIM / 2];        // (g0,g1) per (j, dim-pair)
__device__ float  g_qzT[128 * NPTS];            // [k][i]: k<64 -> q, k>=64 -> z
__device__ float  g_abT[128 * NPTS];            // [k][j]: k<64 -> a, k>=64 -> b
__device__ float  g_gsum[NPTS];                 // sum_d g_jd
__device__ float  g_psum[NPTS * NCHUNK * DDIM]; // per-(i,chunk) per-dim sums of 2^y
__device__ float  g_sm2[NPTS * NJT];            // per-(i,jtile) LSE max (log2)
__device__ float  g_ss2[NPTS * NJT];            // per-(i,jtile) LSE scaled sum
__device__ float  g_val[NPTS];                  // per-i result

static __device__ __forceinline__ float ex2f(float x) {
    float r; asm("ex2.approx.ftz.f32 %0, %1;" : "=f"(r) : "f"(x)); return r;
}
static __device__ __forceinline__ float lg2f(float x) {
    float r; asm("lg2.approx.f32 %0, %1;" : "=f"(r) : "f"(x)); return r;
}
// Pack two fp32 -> half2 (one F2FP.PACK), 2^x on both halves (one MUFU).
static __device__ __forceinline__ __half2 ex2h2(float x, float y) {
    __half2 h = __floats2half2_rn(x, y);
    __half2 r;
    asm("ex2.approx.f16x2 %0, %1;"
        : "=r"(*reinterpret_cast<unsigned*>(&r))
        : "r"(*reinterpret_cast<const unsigned*>(&h)));
    return r;
}

static __device__ __forceinline__ void coeffs(float mm, float lv,
                                              float& a, float& b, float& g) {
    const float iv = ex2f(-LOG2E * lv);          // exp(-lv)
    const float w  = -0.5f * LOG2E * iv;
    const float t  = w * mm;
    a = w;
    b = -(t + t);
    g = fmaf(t, mm, -0.5f * LOG2E * (lv + LOG2PI));
}

// k0: coefficients (packed for kB), GEMM operands (transposed), Gsum.
__global__ __launch_bounds__(256)
void tc_prep_kernel(const float* __restrict__ z,
                    const float* __restrict__ zmean,
                    const float* __restrict__ zlv)
{
    const int e = blockIdx.x * 256 + threadIdx.x;   // [0, 32768)
    const int j = e >> 4;                           // row index
    const int f = e & 15;                           // float4 within row
    const int d0 = 4 * f;
    const float4 mv = ((const float4*)zmean)[e];
    const float4 lv = ((const float4*)zlv)[e];
    float a[4], b[4], g[4];
    coeffs(mv.x, lv.x, a[0], b[0], g[0]);
    coeffs(mv.y, lv.y, a[1], b[1], g[1]);
    coeffs(mv.z, lv.z, a[2], b[2], g[2]);
    coeffs(mv.w, lv.w, a[3], b[3], g[3]);

    // packed layout for kB
    g_cAB[(j << 5) + 2 * f]     = make_float4(a[0], a[1], b[0], b[1]);
    g_cAB[(j << 5) + 2 * f + 1] = make_float4(a[2], a[3], b[2], b[3]);
    g_cG[(j << 5) + 2 * f]      = make_float2(g[0], g[1]);
    g_cG[(j << 5) + 2 * f + 1]  = make_float2(g[2], g[3]);

    // transposed GEMM operand [a|b]
    #pragma unroll
    for (int q = 0; q < 4; ++q) {
        g_abT[(d0 + q) * NPTS + j]      = a[q];
        g_abT[(64 + d0 + q) * NPTS + j] = b[q];
    }

    // Gsum_j: segmented reduce over the 16 threads of row j
    float gs = (g[0] + g[1]) + (g[2] + g[3]);
    #pragma unroll
    for (int off = 1; off <= 8; off <<= 1)
        gs += __shfl_xor_sync(0xffffffffu, gs, off);
    if ((threadIdx.x & 15) == 0) g_gsum[j] = gs;

    // transposed GEMM operand [q|z] (same e covers row j of z)
    const float4 zv = ((const float4*)z)[e];
    const float zq[4] = {zv.x, zv.y, zv.z, zv.w};
    #pragma unroll
    for (int q = 0; q < 4; ++q) {
        g_qzT[(d0 + q) * NPTS + j]      = zq[q] * zq[q];
        g_qzT[(64 + d0 + q) * NPTS + j] = zq[q];
    }
}

// kA: S = QZ . AB^T + Gsum, fused per-(i, jtile) LSE partials.
// Grid 256 blocks (16 x 16 tiles of 128x128), 256 threads, 8x8 micro.
__global__ __launch_bounds__(256, 2)
void tc_sgemm_kernel()
{
    __shared__ float sQZ[KC][128];
    __shared__ float sAB[KC][128];

    const int tid = threadIdx.x;
    const int tx  = tid & 15;          // j direction
    const int ty  = tid >> 4;          // i direction
    const int it  = blockIdx.x >> 4;
    const int jt  = blockIdx.x & 15;

    float acc[8][8];
    #pragma unroll
    for (int r = 0; r < 8; ++r)
        #pragma unroll
        for (int c = 0; c < 8; ++c) acc[r][c] = 0.f;

    for (int kc = 0; kc < 128 / KC; ++kc) {
        __syncthreads();
        #pragma unroll
        for (int f4 = tid; f4 < KC * 32; f4 += 256) {
            const int k  = f4 >> 5;
            const int c4 = f4 & 31;
            ((float4*)sQZ[k])[c4] =
                ((const float4*)(g_qzT + (kc * KC + k) * NPTS + it * 128))[c4];
            ((float4*)sAB[k])[c4] =
                ((const float4*)(g_abT + (kc * KC + k) * NPTS + jt * 128))[c4];
        }
        __syncthreads();

        #pragma unroll 8
        for (int k = 0; k < KC; ++k) {
            const float4 q0 = *(const float4*)&sQZ[k][ty * 8];
            const float4 q1 = *(const float4*)&sQZ[k][ty * 8 + 4];
            const float4 al = *(const float4*)&sAB[k][tx * 4];
            const float4 ah = *(const float4*)&sAB[k][64 + tx * 4];
            const float qr[8] = {q0.x, q0.y, q0.z, q0.w, q1.x, q1.y, q1.z, q1.w};
            const float ac[8] = {al.x, al.y, al.z, al.w, ah.x, ah.y, ah.z, ah.w};
            #pragma unroll
            for (int r = 0; r < 8; ++r)
                #pragma unroll
                for (int c = 0; c < 8; ++c)
                    acc[r][c] = fmaf(qr[r], ac[c], acc[r][c]);
        }
    }

    // epilogue: add Gsum, per-row LSE over this 128-j tile
    const float4 gl = *(const float4*)&g_gsum[jt * 128 + tx * 4];
    const float4 gh = *(const float4*)&g_gsum[jt * 128 + 64 + tx * 4];
    const float gs[8] = {gl.x, gl.y, gl.z, gl.w, gh.x, gh.y, gh.z, gh.w};

    #pragma unroll
    for (int r = 0; r < 8; ++r) {
        float S[8];
        #pragma unroll
        for (int c = 0; c < 8; ++c) S[c] = acc[r][c] + gs[c];
        float m = S[0];
        #pragma unroll
        for (int c = 1; c < 8; ++c) m = fmaxf(m, S[c]);
        #pragma unroll
        for (int off = 1; off <= 8; off <<= 1)
            m = fmaxf(m, __shfl_xor_sync(0xffffffffu, m, off));
        const __half2 h0 = ex2h2(S[0] - m, S[1] - m);
        const __half2 h1 = ex2h2(S[2] - m, S[3] - m);
        const __half2 h2 = ex2h2(S[4] - m, S[5] - m);
        const __half2 h3 = ex2h2(S[6] - m, S[7] - m);
        const __half2 hs = __hadd2(__hadd2(h0, h1), __hadd2(h2, h3));
        const float2 fs = __half22float2(hs);
        float s = fs.x + fs.y;
        #pragma unroll
        for (int off = 1; off <= 8; off <<= 1)
            s += __shfl_xor_sync(0xffffffffu, s, off);
        if (tx == 0) {
            const int i = it * 128 + ty * 8 + r;
            g_sm2[i * NJT + jt] = m;
            g_ss2[i * NJT + jt] = s;
        }
    }
}

// kB: per-dim path only. Warp owns 4 i's; lane owns dims {2l, 2l+1}.
__global__ __launch_bounds__(256, 3)
void tc_main_kernel(const float* __restrict__ z)
{
    __shared__ float4 shAB[TJ * 32];   // 32 KB
    __shared__ float2 shG[TJ * 32];    // 16 KB

    const int tid  = threadIdx.x;
    const int wid  = tid >> 5;
    const unsigned lane = tid & 31;

    for (int u = blockIdx.x; u < NUNITS; u += NBLOCKS_B) {
        const int ig = u & (NGROUP - 1);
        const int c  = u >> 6;
        const int js = c * TJ;

        __syncthreads();  // previous unit's readers done
        {
            const float4* pab = g_cAB + js * 32;
            const float4* pg  = (const float4*)(g_cG + js * 32);
            #pragma unroll
            for (int e = tid; e < TJ * 32; e += 256)
                shAB[e] = pab[e];
            #pragma unroll
            for (int e = tid; e < TJ * 16; e += 256)
                ((float4*)shG)[e] = pg[e];
        }
        __syncthreads();

        const int i0 = ig * IPB + wid * 4;
        float z0[4], z1[4], q0[4], q1[4], ac0[4], ac1[4];
        #pragma unroll
        for (int ii = 0; ii < 4; ++ii) {
            const float2 zv = ((const float2*)z)[(i0 + ii) * 32 + lane];
            z0[ii] = zv.x; z1[ii] = zv.y;
            q0[ii] = zv.x * zv.x; q1[ii] = zv.y * zv.y;
            ac0[ii] = 0.f; ac1[ii] = 0.f;
        }

        #pragma unroll 1
        for (int jb = 0; jb < TJ / 8; ++jb) {
            __half2 eq[4][4];
            #pragma unroll
            for (int k = 0; k < 8; ++k) {
                const int j = jb * 8 + k;
                const float4 ab = shAB[j * 32 + lane];
                const float2 g  = shG[j * 32 + lane];
                #pragma unroll
                for (int ii = 0; ii < 4; ++ii) {
                    const float y0 = fmaf(ab.x, q0[ii], fmaf(ab.z, z0[ii], g.x));
                    const float y1 = fmaf(ab.y, q1[ii], fmaf(ab.w, z1[ii], g.y));
                    const __half2 e = ex2h2(y0, y1);
                    if (k & 1) eq[ii][k >> 1] = __hadd2(eq[ii][k >> 1], e);
                    else       eq[ii][k >> 1] = e;
                }
            }
            #pragma unroll
            for (int ii = 0; ii < 4; ++ii) {
                const __half2 r = __hadd2(__hadd2(eq[ii][0], eq[ii][1]),
                                          __hadd2(eq[ii][2], eq[ii][3]));
                const float2 fv = __half22float2(r);
                ac0[ii] += fv.x;
                ac1[ii] += fv.y;
            }
        }

        #pragma unroll
        for (int ii = 0; ii < 4; ++ii)
            ((float2*)g_psum)[((i0 + ii) * NCHUNK + c) * 32 + lane] =
                make_float2(ac0[ii], ac1[ii]);
    }
}

// kR: one warp per i. Per-dim: sum 32 chunks, sum_d log2. Scalar: merge 16
// (m,s) tile partials via butterfly within 16 lanes.
__global__ __launch_bounds__(256)
void tc_reduce_i()
{
    const int wid  = threadIdx.x >> 5;
    const int lane = threadIdx.x & 31;
    const int i    = blockIdx.x * 8 + wid;

    float s0 = 0.f, s1 = 0.f;
    const float2* P = (const float2*)g_psum;
    #pragma unroll
    for (int cc = 0; cc < NCHUNK; ++cc) {
        const float2 v = P[(i * NCHUNK + cc) * 32 + lane];
        s0 += v.x; s1 += v.y;
    }
    float t = lg2f(s0) + lg2f(s1);
    #pragma unroll
    for (int off = 16; off; off >>= 1)
        t += __shfl_xor_sync(0xffffffffu, t, off);

    float ml = (lane < NJT) ? g_sm2[i * NJT + lane] : -1.0e30f;
    float sl = (lane < NJT) ? g_ss2[i * NJT + lane] : 0.f;
    #pragma unroll
    for (int off = 8; off; off >>= 1) {
        const float mo = __shfl_xor_sync(0xffffffffu, ml, off);
        const float so = __shfl_xor_sync(0xffffffffu, sl, off);
        const float M  = fmaxf(ml, mo);
        sl = sl * ex2f(ml - M) + so * ex2f(mo - M);
        ml = M;
    }

    if (lane == 0)
        g_val[i] = LN2 * (t - (ml + lg2f(sl)));
}

// kF: deterministic final mean.
__global__ __launch_bounds__(256)
void tc_final(float* __restrict__ out)
{
    __shared__ float sm[8];
    const int t = threadIdx.x;
    float v = 0.f;
    #pragma unroll
    for (int k = 0; k < 8; ++k)
        v += g_val[t + k * 256];
    #pragma unroll
    for (int off = 16; off; off >>= 1)
        v += __shfl_xor_sync(0xffffffffu, v, off);
    if ((t & 31) == 0) sm[t >> 5] = v;
    __syncthreads();
    if (t == 0) {
        float r = 0.f;
        #pragma unroll
        for (int k = 0; k < 8; ++k) r += sm[k];
        out[0] = r * (1.0f / (float)NPTS);
    }
}

extern "C" void kernel_launch(void* const* d_in, const int* in_sizes, int n_in,
                              void* d_out, int out_size)
{
    const float* z  = (const float*)d_in[0];
    const float* zm = (const float*)d_in[1];
    const float* zl = (const float*)d_in[2];
    tc_prep_kernel<<<NPTS * DDIM / 1024, 256>>>(z, zm, zl);
    tc_sgemm_kernel<<<256, 256>>>();
    tc_main_kernel<<<NBLOCKS_B, 256>>>(z);
    tc_reduce_i<<<NPTS / 8, 256>>>();
    tc_final<<<1, 256>>>((float*)d_out);
}